// round 11
// baseline (speedup 1.0000x reference)
#include <cuda_runtime.h>
#include <cuda_bf16.h>
#include <math.h>
#include <cstdint>

#define BATCH 4
#define SEQ   2048
#define DIM   1024
#define NHEAD 16
#define HDIM  64
#define QKVN  (3 * DIM)   // 3072

__device__ float g_qkv[(size_t)BATCH * SEQ * QKVN];
__device__ float g_y[(size_t)BATCH * SEQ * DIM];

// ===========================================================================
// Common helpers
// ===========================================================================
__device__ __forceinline__ unsigned f2tf32(float x) {
    unsigned u;
    asm("cvt.rna.tf32.f32 %0, %1;" : "=r"(u) : "f"(x));
    return u;
}

__device__ __forceinline__ void mma_tf32(float c[4], const unsigned a[4], const unsigned b[2]) {
    asm volatile(
        "mma.sync.aligned.m16n8k8.row.col.f32.tf32.tf32.f32 "
        "{%0,%1,%2,%3}, {%4,%5,%6,%7}, {%8,%9}, {%0,%1,%2,%3};\n"
        : "+f"(c[0]), "+f"(c[1]), "+f"(c[2]), "+f"(c[3])
        : "r"(a[0]), "r"(a[1]), "r"(a[2]), "r"(a[3]),
          "r"(b[0]), "r"(b[1]));
}

__device__ __forceinline__ uint32_t smem_u32(const void* p) {
    uint32_t a;
    asm("{ .reg .u64 t; cvta.to.shared.u64 t, %1; cvt.u32.u64 %0, t; }"
        : "=r"(a) : "l"(p));
    return a;
}

__device__ __forceinline__ void cpa16(uint32_t dst, const void* src) {
    asm volatile("cp.async.cg.shared.global [%0], [%1], 16;\n"
                 :: "r"(dst), "l"(src) : "memory");
}

// ===========================================================================
// TF32 mma.sync GEMM v3: C[M,N] = A[M,K] @ B[K,N] + bias[N]
// CTA 128x256, BK=32, 256 threads = 8 warps (2m x 4n grid of 64x64 tiles).
// cp.async double-buffered smem (raw fp32); cvt->tf32 at fragment load.
// Conflict-free fragment strides: A stride 36 (==4 mod 32) -> banks 4g+t,
// B stride 264 (==8 mod 32) -> banks 8t+g.
// ===========================================================================
#define AST2 36                       // floats per A smem row (32 data + 4 pad)
#define BST3 264                      // floats per B smem row (256 data + 8 pad)
#define A_STAGE (128 * AST2)          // 4608 floats = 18432 B
#define B_STAGE3 (32 * BST3)          // 8448 floats = 33792 B
#define GSMEM_BYTES ((2 * A_STAGE + 2 * B_STAGE3) * 4)   // 104448 B

__global__ __launch_bounds__(256) void gemm_mma_kernel(
    const float* __restrict__ A, const float* __restrict__ Bw,
    const float* __restrict__ bias, float* __restrict__ C,
    int N, int K)
{
    extern __shared__ float smem[];
    float* sA = smem;                      // 2 stages of A
    float* sB = smem + 2 * A_STAGE;        // 2 stages of B
    const uint32_t sAu = smem_u32(sA);
    const uint32_t sBu = smem_u32(sB);

    const int tid  = threadIdx.x;
    const int wid  = tid >> 5;
    const int lid  = tid & 31;
    const int wm   = wid & 1;              // m offset wm*64
    const int wn   = wid >> 1;             // n offset wn*64 (0..3)
    const int g    = lid >> 2;             // 0..7
    const int t    = lid & 3;              // 0..3
    const int row0 = blockIdx.y * 128;
    const int col0 = blockIdx.x * 256;

    float acc[4][8][4];
#pragma unroll
    for (int mt = 0; mt < 4; mt++)
#pragma unroll
        for (int nt = 0; nt < 8; nt++)
#pragma unroll
            for (int i = 0; i < 4; i++) acc[mt][nt][i] = 0.f;

    const int NIT = K / 32;

    // ---- stage loader ----
    // A tile: 128 rows x 32 floats = 1024 16B-chunks (8/row), 4 iters x 256 thr
    // B tile:  32 rows x 256 floats = 2048 16B-chunks (64/row), 8 iters x 256 thr
    auto load_stage = [&](int it, int st) {
        const int k0 = it * 32;
        const uint32_t aBase = sAu + (uint32_t)st * A_STAGE * 4;
        const uint32_t bBase = sBu + (uint32_t)st * B_STAGE3 * 4;
#pragma unroll
        for (int i = 0; i < 4; i++) {
            const int c  = tid + i * 256;
            const int m  = c >> 3;              // 0..127
            const int ch = c & 7;               // 0..7 -> k float offset ch*4
            cpa16(aBase + (uint32_t)(m * AST2 + ch * 4) * 4,
                  &A[(size_t)(row0 + m) * K + k0 + ch * 4]);
        }
#pragma unroll
        for (int i = 0; i < 8; i++) {
            const int c  = tid + i * 256;
            const int r  = c >> 6;              // 0..31 (k row)
            const int ch = c & 63;              // 0..63 -> n float offset ch*4
            cpa16(bBase + (uint32_t)(r * BST3 + ch * 4) * 4,
                  &Bw[(size_t)(k0 + r) * N + col0 + ch * 4]);
        }
        asm volatile("cp.async.commit_group;\n" ::: "memory");
    };

    load_stage(0, 0);

    for (int it = 0; it < NIT; it++) {
        if (it + 1 < NIT) {
            load_stage(it + 1, (it + 1) & 1);
            asm volatile("cp.async.wait_group 1;\n" ::: "memory");
        } else {
            asm volatile("cp.async.wait_group 0;\n" ::: "memory");
        }
        __syncthreads();

        const float* As_ = sA + (it & 1) * A_STAGE;
        const float* Bs_ = sB + (it & 1) * B_STAGE3;

#pragma unroll
        for (int ks = 0; ks < 4; ks++) {
            const int ko = ks * 8;
            unsigned a_[4][4];
#pragma unroll
            for (int mt = 0; mt < 4; mt++) {
                const int mo = wm * 64 + mt * 16;
                a_[mt][0] = f2tf32(As_[(mo + g)     * AST2 + ko + t]);
                a_[mt][1] = f2tf32(As_[(mo + g + 8) * AST2 + ko + t]);
                a_[mt][2] = f2tf32(As_[(mo + g)     * AST2 + ko + t + 4]);
                a_[mt][3] = f2tf32(As_[(mo + g + 8) * AST2 + ko + t + 4]);
            }
            unsigned b_[8][2];
#pragma unroll
            for (int nt = 0; nt < 8; nt++) {
                const int no = wn * 64 + nt * 8;
                b_[nt][0] = f2tf32(Bs_[(ko + t)     * BST3 + no + g]);
                b_[nt][1] = f2tf32(Bs_[(ko + t + 4) * BST3 + no + g]);
            }
#pragma unroll
            for (int mt = 0; mt < 4; mt++)
#pragma unroll
                for (int nt = 0; nt < 8; nt++)
                    mma_tf32(acc[mt][nt], a_[mt], b_[nt]);
        }
        __syncthreads();
    }

    // ---- epilogue: bias + float2 stores ----
#pragma unroll
    for (int mt = 0; mt < 4; mt++) {
        const int r0 = row0 + wm * 64 + mt * 16 + g;
#pragma unroll
        for (int nt = 0; nt < 8; nt++) {
            const int c = col0 + wn * 64 + nt * 8 + 2 * t;
            const float b0 = __ldg(&bias[c]);
            const float b1 = __ldg(&bias[c + 1]);
            float2 v0, v1;
            v0.x = acc[mt][nt][0] + b0;
            v0.y = acc[mt][nt][1] + b1;
            v1.x = acc[mt][nt][2] + b0;
            v1.y = acc[mt][nt][3] + b1;
            *(float2*)&C[(size_t)r0 * N + c]       = v0;
            *(float2*)&C[(size_t)(r0 + 8) * N + c] = v1;
        }
    }
}

// ===========================================================================
// TF32 mma.sync causal flash attention (unchanged — passing at ~370us)
// ===========================================================================
#define QSTR 68
#define KSTR 68
#define VSTR 72
#define PSTR 68

__global__ __launch_bounds__(256, 2) void attn_mma_kernel(
    const float* __restrict__ qkv, float* __restrict__ y)
{
    extern __shared__ float sm[];
    float* Qs = sm;
    float* Ks = Qs + 128 * QSTR;
    float* Vs = Ks + 64 * KSTR;
    float* Ps = Vs + 64 * VSTR;

    const int qt  = blockIdx.x;
    const int h   = blockIdx.y;
    const int b   = blockIdx.z;
    const int tid = threadIdx.x;
    const int wid = tid >> 5;
    const int lid = tid & 31;
    const int g   = lid >> 2;
    const int t   = lid & 3;
    const int q0  = qt * 128;

    const size_t base = (size_t)b * SEQ * QKVN + h * HDIM;

    {
        const int lr = tid >> 4;
        const int c4 = (tid & 15) * 4;
#pragma unroll
        for (int p = 0; p < 8; p++) {
            const int row = lr + p * 16;
            float4 v = *(const float4*)&qkv[base + (size_t)(q0 + row) * QKVN + c4];
            uint4 u;
            u.x = f2tf32(v.x * 0.125f);
            u.y = f2tf32(v.y * 0.125f);
            u.z = f2tf32(v.z * 0.125f);
            u.w = f2tf32(v.w * 0.125f);
            *(uint4*)&Qs[row * QSTR + c4] = u;
        }
    }

    float m0 = -INFINITY, m1 = -INFINITY;
    float l0 = 0.f, l1 = 0.f;
    float O[8][4];
#pragma unroll
    for (int nt = 0; nt < 8; nt++)
#pragma unroll
        for (int i = 0; i < 4; i++) O[nt][i] = 0.f;

    const int warp_row = q0 + wid * 16;
    const int ktiles = 2 * qt + 2;

    for (int kt = 0; kt < ktiles; kt++) {
        const int k0 = kt * 64;
        __syncthreads();

        {
            const int lr = tid >> 4;
            const int c4 = (tid & 15) * 4;
#pragma unroll
            for (int p = 0; p < 4; p++) {
                const int row = lr + p * 16;
                const size_t gbase = base + (size_t)(k0 + row) * QKVN + c4;
                float4 kv = *(const float4*)&qkv[gbase + DIM];
                float4 vv = *(const float4*)&qkv[gbase + 2 * DIM];
                uint4 ku, vu;
                ku.x = f2tf32(kv.x); ku.y = f2tf32(kv.y);
                ku.z = f2tf32(kv.z); ku.w = f2tf32(kv.w);
                vu.x = f2tf32(vv.x); vu.y = f2tf32(vv.y);
                vu.z = f2tf32(vv.z); vu.w = f2tf32(vv.w);
                *(uint4*)&Ks[row * KSTR + c4] = ku;
                *(uint4*)&Vs[row * VSTR + c4] = vu;
            }
        }
        __syncthreads();

        if (k0 <= warp_row + 15) {
            float s[8][4];
#pragma unroll
            for (int nt = 0; nt < 8; nt++)
#pragma unroll
                for (int i = 0; i < 4; i++) s[nt][i] = 0.f;

#pragma unroll
            for (int ks = 0; ks < 8; ks++) {
                const int ko = ks * 8;
                unsigned a_[4], b_[2];
                a_[0] = __float_as_uint(Qs[(wid * 16 + g)     * QSTR + ko + t]);
                a_[1] = __float_as_uint(Qs[(wid * 16 + g + 8) * QSTR + ko + t]);
                a_[2] = __float_as_uint(Qs[(wid * 16 + g)     * QSTR + ko + t + 4]);
                a_[3] = __float_as_uint(Qs[(wid * 16 + g + 8) * QSTR + ko + t + 4]);
#pragma unroll
                for (int nt = 0; nt < 8; nt++) {
                    b_[0] = __float_as_uint(Ks[(nt * 8 + g) * KSTR + ko + t]);
                    b_[1] = __float_as_uint(Ks[(nt * 8 + g) * KSTR + ko + t + 4]);
                    mma_tf32(s[nt], a_, b_);
                }
            }

            const int r0g = warp_row + g;
            if (k0 + 63 > r0g) {
#pragma unroll
                for (int nt = 0; nt < 8; nt++) {
                    const int c0 = k0 + nt * 8 + 2 * t;
                    if (c0     > r0g)     s[nt][0] = -INFINITY;
                    if (c0 + 1 > r0g)     s[nt][1] = -INFINITY;
                    if (c0     > r0g + 8) s[nt][2] = -INFINITY;
                    if (c0 + 1 > r0g + 8) s[nt][3] = -INFINITY;
                }
            }

            float mt0 = -INFINITY, mt1 = -INFINITY;
#pragma unroll
            for (int nt = 0; nt < 8; nt++) {
                mt0 = fmaxf(mt0, fmaxf(s[nt][0], s[nt][1]));
                mt1 = fmaxf(mt1, fmaxf(s[nt][2], s[nt][3]));
            }
            mt0 = fmaxf(mt0, __shfl_xor_sync(0xffffffffu, mt0, 1));
            mt0 = fmaxf(mt0, __shfl_xor_sync(0xffffffffu, mt0, 2));
            mt1 = fmaxf(mt1, __shfl_xor_sync(0xffffffffu, mt1, 1));
            mt1 = fmaxf(mt1, __shfl_xor_sync(0xffffffffu, mt1, 2));

            const float m0n = fmaxf(m0, mt0);
            const float m1n = fmaxf(m1, mt1);
            const float c0f = __expf(m0 - m0n);
            const float c1f = __expf(m1 - m1n);

            float sum0 = 0.f, sum1 = 0.f;
#pragma unroll
            for (int nt = 0; nt < 8; nt++) {
                const float p0 = __expf(s[nt][0] - m0n);
                const float p1 = __expf(s[nt][1] - m0n);
                const float p2 = __expf(s[nt][2] - m1n);
                const float p3 = __expf(s[nt][3] - m1n);
                sum0 += p0 + p1;
                sum1 += p2 + p3;
                float2 w0, w1;
                w0.x = __uint_as_float(f2tf32(p0));
                w0.y = __uint_as_float(f2tf32(p1));
                w1.x = __uint_as_float(f2tf32(p2));
                w1.y = __uint_as_float(f2tf32(p3));
                *(float2*)&Ps[(wid * 16 + g)     * PSTR + nt * 8 + 2 * t] = w0;
                *(float2*)&Ps[(wid * 16 + g + 8) * PSTR + nt * 8 + 2 * t] = w1;
            }
            sum0 += __shfl_xor_sync(0xffffffffu, sum0, 1);
            sum0 += __shfl_xor_sync(0xffffffffu, sum0, 2);
            sum1 += __shfl_xor_sync(0xffffffffu, sum1, 1);
            sum1 += __shfl_xor_sync(0xffffffffu, sum1, 2);

            l0 = l0 * c0f + sum0;
            l1 = l1 * c1f + sum1;
            m0 = m0n;
            m1 = m1n;
#pragma unroll
            for (int nt = 0; nt < 8; nt++) {
                O[nt][0] *= c0f; O[nt][1] *= c0f;
                O[nt][2] *= c1f; O[nt][3] *= c1f;
            }

            __syncwarp();

#pragma unroll
            for (int ks = 0; ks < 8; ks++) {
                const int ko = ks * 8;
                unsigned a_[4], b_[2];
                a_[0] = __float_as_uint(Ps[(wid * 16 + g)     * PSTR + ko + t]);
                a_[1] = __float_as_uint(Ps[(wid * 16 + g + 8) * PSTR + ko + t]);
                a_[2] = __float_as_uint(Ps[(wid * 16 + g)     * PSTR + ko + t + 4]);
                a_[3] = __float_as_uint(Ps[(wid * 16 + g + 8) * PSTR + ko + t + 4]);
#pragma unroll
                for (int nt = 0; nt < 8; nt++) {
                    b_[0] = __float_as_uint(Vs[(ko + t)     * VSTR + nt * 8 + g]);
                    b_[1] = __float_as_uint(Vs[(ko + t + 4) * VSTR + nt * 8 + g]);
                    mma_tf32(O[nt], a_, b_);
                }
            }
        }
    }

    const float inv0 = 1.f / l0;
    const float inv1 = 1.f / l1;
    const int r0 = q0 + wid * 16 + g;
    const size_t y0 = ((size_t)b * SEQ + r0) * DIM + h * HDIM;
    const size_t y1 = y0 + 8 * DIM;
#pragma unroll
    for (int nt = 0; nt < 8; nt++) {
        const int c = nt * 8 + 2 * t;
        float2 o0, o1;
        o0.x = O[nt][0] * inv0; o0.y = O[nt][1] * inv0;
        o1.x = O[nt][2] * inv1; o1.y = O[nt][3] * inv1;
        *(float2*)&y[y0 + c] = o0;
        *(float2*)&y[y1 + c] = o1;
    }
}

// ===========================================================================
// Launch
// ===========================================================================
extern "C" void kernel_launch(void* const* d_in, const int* in_sizes, int n_in,
                              void* d_out, int out_size)
{
    const float* x      = (const float*)d_in[0];
    const float* W_attn = (const float*)d_in[1];
    const float* b_attn = (const float*)d_in[2];
    const float* W_proj = (const float*)d_in[3];
    const float* b_proj = (const float*)d_in[4];
    float* out = (float*)d_out;

    void* qkv_p = nullptr;
    void* y_p   = nullptr;
    cudaGetSymbolAddress(&qkv_p, g_qkv);
    cudaGetSymbolAddress(&y_p, g_y);
    float* qkv = (float*)qkv_p;
    float* y   = (float*)y_p;

    const int M = BATCH * SEQ;  // 8192

    cudaFuncSetAttribute(gemm_mma_kernel,
                         cudaFuncAttributeMaxDynamicSharedMemorySize, GSMEM_BYTES);

    // 1) QKV projection: [8192,1024] @ [1024,3072] + bias
    {
        dim3 grid(QKVN / 256, M / 128);
        gemm_mma_kernel<<<grid, 256, GSMEM_BYTES>>>(x, W_attn, b_attn, qkv, QKVN, DIM);
    }

    // 2) Causal flash attention (tf32 mma.sync)
    {
        const int smem = (128 * QSTR + 64 * KSTR + 64 * VSTR + 128 * PSTR) * (int)sizeof(float);
        cudaFuncSetAttribute(attn_mma_kernel, cudaFuncAttributeMaxDynamicSharedMemorySize, smem);
        dim3 grid(SEQ / 128, NHEAD, BATCH);
        attn_mma_kernel<<<grid, 256, smem>>>(qkv, y);
    }

    // 3) Output projection: [8192,1024] @ [1024,1024] + bias
    {
        dim3 grid(DIM / 256, M / 128);
        gemm_mma_kernel<<<grid, 256, GSMEM_BYTES>>>(y, W_proj, b_proj, out, DIM, DIM);
    }
}